// round 10
// baseline (speedup 1.0000x reference)
#include <cuda_runtime.h>
#include <cuda_bf16.h>
#include <cstdint>

// GRU_66314295050287 on GB300 (sm_103a) — R10: occupancy push.
// R9's independent per-warp cp.async pipelines, but with both occupancy
// limiters shrunk: launch_bounds(32,24) caps regs at ~85 (RF: 24*32*85=65K),
// and CHUNK_F=2 halves the smem buffers to 7.4 KB/block (smem allows 30).
// -> ~24 resident 1-warp blocks per SM vs ~13 before.

#define T_DIM        12
#define FE_DIM       32
#define SEQ_PER_BLK  32
#define NTHREADS     32
#define CHUNK_F      2
#define NCHUNKS      (FE_DIM / CHUNK_F)          // 16
#define CHUNK_FLOATS (CHUNK_F * T_DIM)           // 24
#define CHUNK_VEC4   (CHUNK_FLOATS / 4)          // 6 float4 per seq per chunk
#define SSTRIDE      28                          // 28l mod 32 distinct per phase
#define NBUF         2
#define BUF_FLOATS   (SEQ_PER_BLK * SSTRIDE)     // 896 floats per buffer
#define SEQ_VEC4     96                          // 1536 B per sequence

__device__ __forceinline__ float fast_sigmoid(float x) {
    return 1.0f / (1.0f + __expf(-x));
}
__device__ __forceinline__ float fast_tanh(float x) {
    float e = __expf(2.0f * x);
    return 1.0f - 2.0f / (1.0f + e);
}

__device__ __forceinline__ void cp_async16(unsigned int saddr, const void* gptr) {
    asm volatile("cp.async.cg.shared.global [%0], [%1], 16;\n" :: "r"(saddr), "l"(gptr));
}
__device__ __forceinline__ void cp_commit() {
    asm volatile("cp.async.commit_group;\n");
}
template <int N>
__device__ __forceinline__ void cp_wait() {
    asm volatile("cp.async.wait_group %0;\n" :: "n"(N));
}

extern __shared__ float smem[];

__global__ void __launch_bounds__(NTHREADS, 24)
gru_kernel(const float* __restrict__ x,
           const float* __restrict__ w_ih,   // [3][32]
           const float* __restrict__ w_hh,   // [3][1]
           const float* __restrict__ b_ih,   // [3]
           const float* __restrict__ b_hh,   // [3]
           const float* __restrict__ lin_w,  // [3][12]
           const float* __restrict__ lin_b,  // [3]
           float* __restrict__ out)          // [M][3]
{
    float* buf0  = smem;                        // NBUF x BUF_FLOATS
    float* s_wih = smem + NBUF * BUF_FLOATS;    // 96
    float* s_lw  = s_wih + 96;                  // 36

    const int tid = threadIdx.x;
#pragma unroll
    for (int i = tid; i < 96; i += NTHREADS) s_wih[i] = w_ih[i];
#pragma unroll
    for (int i = tid; i < 36; i += NTHREADS) s_lw[i] = lin_w[i];

    const int m0 = blockIdx.x * SEQ_PER_BLK;
    const float4* __restrict__ x4 = reinterpret_cast<const float4*>(x);

    const unsigned int sbase = (unsigned int)__cvta_generic_to_shared(buf0);

    // Issue one chunk's loads into buffer b: 32 seq * 6 float4 -> 6 per lane.
    auto issue_chunk = [&](int c, int b) {
#pragma unroll
        for (int k = 0; k < (SEQ_PER_BLK * CHUNK_VEC4) / NTHREADS; ++k) {
            int i  = k * NTHREADS + tid;
            int ms = i / CHUNK_VEC4;
            int q  = i - ms * CHUNK_VEC4;
            const void* g = (const void*)(x4 + (long)(m0 + ms) * SEQ_VEC4 + c * CHUNK_VEC4 + q);
            unsigned int s = sbase + (unsigned int)((b * BUF_FLOATS + ms * SSTRIDE + q * 4) * 4);
            cp_async16(s, g);
        }
        cp_commit();
    };

    const float bi0 = b_ih[0], bi1 = b_ih[1], bi2 = b_ih[2];
    float gx0[T_DIM], gx1[T_DIM], gx2[T_DIM];
#pragma unroll
    for (int t = 0; t < T_DIM; ++t) { gx0[t] = bi0; gx1[t] = bi1; gx2[t] = bi2; }

    issue_chunk(0, 0);

#pragma unroll
    for (int c = 0; c < NCHUNKS; ++c) {
        // Buffer (c+1)&1 was fully consumed at iteration c-1 (trailing barrier)
        // -> safe to refill before waiting on chunk c.
        if (c + 1 < NCHUNKS) {
            issue_chunk(c + 1, (c + 1) & 1);
            cp_wait<1>();           // chunk c landed; c+1 in flight
        } else {
            cp_wait<0>();
        }
        __syncthreads();            // 1-warp block: BAR floor; chunk c visible

        const float* my = buf0 + (c & 1) * BUF_FLOATS + tid * SSTRIDE;
#pragma unroll
        for (int fl = 0; fl < CHUNK_F; ++fl) {
            int f = c * CHUNK_F + fl;
            float w0 = s_wih[f];
            float w1 = s_wih[32 + f];
            float w2 = s_wih[64 + f];
            float4 a = reinterpret_cast<const float4*>(my + fl * T_DIM)[0];
            float4 b = reinterpret_cast<const float4*>(my + fl * T_DIM)[1];
            float4 d = reinterpret_cast<const float4*>(my + fl * T_DIM)[2];
            float xt[T_DIM] = {a.x, a.y, a.z, a.w, b.x, b.y, b.z, b.w, d.x, d.y, d.z, d.w};
#pragma unroll
            for (int t = 0; t < T_DIM; ++t) {
                gx0[t] = fmaf(xt[t], w0, gx0[t]);
                gx1[t] = fmaf(xt[t], w1, gx1[t]);
                gx2[t] = fmaf(xt[t], w2, gx2[t]);
            }
        }
        __syncthreads();            // buffer c consumed -> refillable
    }

    // Scalar-hidden GRU recurrence + relu + linear head.
    const float wh0 = w_hh[0], wh1 = w_hh[1], wh2 = w_hh[2];
    const float bh0 = b_hh[0], bh1 = b_hh[1], bh2 = b_hh[2];
    float o0 = lin_b[0], o1 = lin_b[1], o2 = lin_b[2];
    float h = 0.0f;
#pragma unroll
    for (int t = 0; t < T_DIM; ++t) {
        float r = fast_sigmoid(gx0[t] + wh0 * h + bh0);
        float z = fast_sigmoid(gx1[t] + wh1 * h + bh1);
        float n = fast_tanh(gx2[t] + r * (wh2 * h + bh2));
        h = (1.0f - z) * n + z * h;
        float hr = fmaxf(h, 0.0f);
        o0 = fmaf(hr, s_lw[t],       o0);
        o1 = fmaf(hr, s_lw[12 + t],  o1);
        o2 = fmaf(hr, s_lw[24 + t],  o2);
    }

    // Coalesced epilogue: stage [32][3] floats in smem, write 24 float4.
    float* s_out = buf0;            // reuse (trailing barrier covered final reads)
    s_out[tid * 3 + 0] = o0;        // stride 3 coprime with 32 -> conflict-free
    s_out[tid * 3 + 1] = o1;
    s_out[tid * 3 + 2] = o2;
    __syncthreads();
    if (tid < (SEQ_PER_BLK * 3) / 4) {
        reinterpret_cast<float4*>(out + (long)m0 * 3)[tid] =
            reinterpret_cast<const float4*>(s_out)[tid];
    }
}

extern "C" void kernel_launch(void* const* d_in, const int* in_sizes, int n_in,
                              void* d_out, int out_size) {
    const float* x     = (const float*)d_in[0];
    const float* w_ih  = (const float*)d_in[1];
    const float* w_hh  = (const float*)d_in[2];
    const float* b_ih  = (const float*)d_in[3];
    const float* b_hh  = (const float*)d_in[4];
    const float* lin_w = (const float*)d_in[5];
    const float* lin_b = (const float*)d_in[6];
    float* out = (float*)d_out;

    const int M = in_sizes[0] / (FE_DIM * T_DIM);   // 65536
    const int grid = M / SEQ_PER_BLK;               // 2048

    const size_t smem_bytes = (size_t)(NBUF * BUF_FLOATS + 96 + 36) * sizeof(float);
    cudaFuncSetAttribute(gru_kernel, cudaFuncAttributeMaxDynamicSharedMemorySize,
                         (int)smem_bytes);

    gru_kernel<<<grid, NTHREADS, smem_bytes>>>(x, w_ih, w_hh, b_ih, b_hh,
                                               lin_w, lin_b, out);
}

// round 11
// speedup vs baseline: 1.0714x; 1.0714x over previous
#include <cuda_runtime.h>
#include <cuda_bf16.h>
#include <cstdint>

// GRU_66314295050287 on GB300 (sm_103a) — R11: break the grid-occupancy cap.
// Diagnosis: occ was pinned at ~20% in ALL prior rounds because grid size
// (2048 one-warp blocks / 148 SMs = 13.8 warps/SM) was the binding limit.
// Fix: split each sequence's FE dimension 2-ways within a warp.
//   Block = 32 threads = 16 seqs; lane l: seq l%16, f-half l/16.
//   Grid = 4096 -> 27.7 warps/SM offered; regs<=93 -> 22 resident (occ 34%).
//   Accumulators combined with one shfl_xor(16)+add round (warp-local).

#define T_DIM        12
#define FE_DIM       32
#define SEQ_PER_BLK  16
#define NTHREADS     32
#define CHUNK_F      2                            // f per chunk PER HALF
#define NCHUNKS      8
#define WIN_FLOATS   (CHUNK_F * T_DIM)            // 24 floats per half-window
#define SEQ_CHUNK_FL (2 * WIN_FLOATS)             // 48 floats per seq per chunk
#define SSTRIDE      (SEQ_CHUNK_FL + 4)           // 52: l*52%32=20l -> conflict-free
#define NBUF         2
#define BUF_FLOATS   (SEQ_PER_BLK * SSTRIDE)      // 832 floats per buffer
#define SEQ_VEC4     96                           // 1536 B per sequence
#define CHUNK_VEC4   (SEQ_PER_BLK * SEQ_CHUNK_FL / 4)   // 192 float4 per chunk

__device__ __forceinline__ float fast_sigmoid(float x) {
    return 1.0f / (1.0f + __expf(-x));
}
__device__ __forceinline__ float fast_tanh(float x) {
    float e = __expf(2.0f * x);
    return 1.0f - 2.0f / (1.0f + e);
}

__device__ __forceinline__ void cp_async16(unsigned int saddr, const void* gptr) {
    asm volatile("cp.async.cg.shared.global [%0], [%1], 16;\n" :: "r"(saddr), "l"(gptr));
}
__device__ __forceinline__ void cp_commit() {
    asm volatile("cp.async.commit_group;\n");
}
template <int N>
__device__ __forceinline__ void cp_wait() {
    asm volatile("cp.async.wait_group %0;\n" :: "n"(N));
}

extern __shared__ float smem[];

__global__ void __launch_bounds__(NTHREADS, 22)
gru_kernel(const float* __restrict__ x,
           const float* __restrict__ w_ih,   // [3][32]
           const float* __restrict__ w_hh,   // [3][1]
           const float* __restrict__ b_ih,   // [3]
           const float* __restrict__ b_hh,   // [3]
           const float* __restrict__ lin_w,  // [3][12]
           const float* __restrict__ lin_b,  // [3]
           float* __restrict__ out)          // [M][3]
{
    float* buf0  = smem;                        // NBUF x BUF_FLOATS
    float* s_wih = smem + NBUF * BUF_FLOATS;    // 96
    float* s_lw  = s_wih + 96;                  // 36

    const int tid  = threadIdx.x;
    const int seq  = tid & 15;                  // lane's sequence within block
    const int half = tid >> 4;                  // 0: f 0..15, 1: f 16..31

#pragma unroll
    for (int i = tid; i < 96; i += NTHREADS) s_wih[i] = w_ih[i];
#pragma unroll
    for (int i = tid; i < 36; i += NTHREADS) s_lw[i] = lin_w[i];

    const int m0 = blockIdx.x * SEQ_PER_BLK;
    const float4* __restrict__ x4 = reinterpret_cast<const float4*>(x);
    const unsigned int sbase = (unsigned int)__cvta_generic_to_shared(buf0);

    // Load one chunk: for every seq, two contiguous 24-float windows
    //   low  half: floats [24c, 24c+24)        (f = 2c, 2c+1)
    //   high half: floats [192+24c, 192+24c+24) (f = 16+2c, 16+2c+1)
    // 192 float4 total -> 6 per lane; each window = 6 contiguous float4.
    auto issue_chunk = [&](int c, int b) {
#pragma unroll
        for (int k = 0; k < CHUNK_VEC4 / NTHREADS; ++k) {
            int i  = k * NTHREADS + tid;
            int ms = i / 12;                    // sequence
            int j  = i - ms * 12;               // 0..11 (6 low + 6 high float4)
            int g4 = (j < 6) ? (6 * c + j) : (48 + 6 * c + (j - 6));
            const void* g = (const void*)(x4 + (long)(m0 + ms) * SEQ_VEC4 + g4);
            unsigned int s = sbase + (unsigned int)((b * BUF_FLOATS + ms * SSTRIDE + j * 4) * 4);
            cp_async16(s, g);
        }
        cp_commit();
    };

    // Accumulators: bias folded in on the low half only (summed later).
    float gx0[T_DIM], gx1[T_DIM], gx2[T_DIM];
    {
        const float bi0 = half ? 0.0f : b_ih[0];
        const float bi1 = half ? 0.0f : b_ih[1];
        const float bi2 = half ? 0.0f : b_ih[2];
#pragma unroll
        for (int t = 0; t < T_DIM; ++t) { gx0[t] = bi0; gx1[t] = bi1; gx2[t] = bi2; }
    }

    issue_chunk(0, 0);

#pragma unroll
    for (int c = 0; c < NCHUNKS; ++c) {
        if (c + 1 < NCHUNKS) {
            issue_chunk(c + 1, (c + 1) & 1);
            cp_wait<1>();           // chunk c landed; c+1 in flight
        } else {
            cp_wait<0>();
        }
        __syncthreads();            // 1-warp block: BAR floor; chunk c visible

        const float* my = buf0 + (c & 1) * BUF_FLOATS + seq * SSTRIDE + half * WIN_FLOATS;
#pragma unroll
        for (int fl = 0; fl < CHUNK_F; ++fl) {
            int f = half * 16 + c * CHUNK_F + fl;
            float w0 = s_wih[f];
            float w1 = s_wih[32 + f];
            float w2 = s_wih[64 + f];
            // float4-at-a-time keeps live registers low (no xt[12] array).
#pragma unroll
            for (int v = 0; v < 3; ++v) {
                float4 a = reinterpret_cast<const float4*>(my + fl * T_DIM)[v];
                int tb = v * 4;
                gx0[tb+0] = fmaf(a.x, w0, gx0[tb+0]);
                gx1[tb+0] = fmaf(a.x, w1, gx1[tb+0]);
                gx2[tb+0] = fmaf(a.x, w2, gx2[tb+0]);
                gx0[tb+1] = fmaf(a.y, w0, gx0[tb+1]);
                gx1[tb+1] = fmaf(a.y, w1, gx1[tb+1]);
                gx2[tb+1] = fmaf(a.y, w2, gx2[tb+1]);
                gx0[tb+2] = fmaf(a.z, w0, gx0[tb+2]);
                gx1[tb+2] = fmaf(a.z, w1, gx1[tb+2]);
                gx2[tb+2] = fmaf(a.z, w2, gx2[tb+2]);
                gx0[tb+3] = fmaf(a.w, w0, gx0[tb+3]);
                gx1[tb+3] = fmaf(a.w, w1, gx1[tb+3]);
                gx2[tb+3] = fmaf(a.w, w2, gx2[tb+3]);
            }
        }
        __syncthreads();            // buffer c consumed -> refillable
    }

    // Combine the two f-halves: shfl_xor(16) gives both lanes the pair sum.
#pragma unroll
    for (int t = 0; t < T_DIM; ++t) {
        gx0[t] += __shfl_xor_sync(0xffffffffu, gx0[t], 16);
        gx1[t] += __shfl_xor_sync(0xffffffffu, gx1[t], 16);
        gx2[t] += __shfl_xor_sync(0xffffffffu, gx2[t], 16);
    }

    // Scalar-hidden GRU recurrence + relu + linear head (all lanes, redundant
    // across halves -- cheap, keeps the warp convergent).
    const float wh0 = w_hh[0], wh1 = w_hh[1], wh2 = w_hh[2];
    const float bh0 = b_hh[0], bh1 = b_hh[1], bh2 = b_hh[2];
    float o0 = lin_b[0], o1 = lin_b[1], o2 = lin_b[2];
    float h = 0.0f;
#pragma unroll
    for (int t = 0; t < T_DIM; ++t) {
        float r = fast_sigmoid(gx0[t] + wh0 * h + bh0);
        float z = fast_sigmoid(gx1[t] + wh1 * h + bh1);
        float n = fast_tanh(gx2[t] + r * (wh2 * h + bh2));
        h = (1.0f - z) * n + z * h;
        float hr = fmaxf(h, 0.0f);
        o0 = fmaf(hr, s_lw[t],       o0);
        o1 = fmaf(hr, s_lw[12 + t],  o1);
        o2 = fmaf(hr, s_lw[24 + t],  o2);
    }

    // Coalesced epilogue: lanes of half 0 stage [16][3] floats, write 12 float4.
    float* s_out = buf0;            // reuse (trailing barrier covered final reads)
    if (half == 0) {
        s_out[seq * 3 + 0] = o0;
        s_out[seq * 3 + 1] = o1;
        s_out[seq * 3 + 2] = o2;
    }
    __syncthreads();
    if (tid < (SEQ_PER_BLK * 3) / 4) {
        reinterpret_cast<float4*>(out + (long)m0 * 3)[tid] =
            reinterpret_cast<const float4*>(s_out)[tid];
    }
}

extern "C" void kernel_launch(void* const* d_in, const int* in_sizes, int n_in,
                              void* d_out, int out_size) {
    const float* x     = (const float*)d_in[0];
    const float* w_ih  = (const float*)d_in[1];
    const float* w_hh  = (const float*)d_in[2];
    const float* b_ih  = (const float*)d_in[3];
    const float* b_hh  = (const float*)d_in[4];
    const float* lin_w = (const float*)d_in[5];
    const float* lin_b = (const float*)d_in[6];
    float* out = (float*)d_out;

    const int M = in_sizes[0] / (FE_DIM * T_DIM);   // 65536
    const int grid = M / SEQ_PER_BLK;               // 4096

    const size_t smem_bytes = (size_t)(NBUF * BUF_FLOATS + 96 + 36) * sizeof(float);
    cudaFuncSetAttribute(gru_kernel, cudaFuncAttributeMaxDynamicSharedMemorySize,
                         (int)smem_bytes);

    gru_kernel<<<grid, NTHREADS, smem_bytes>>>(x, w_ih, w_hh, b_ih, b_hh,
                                               lin_w, lin_b, out);
}

// round 12
// speedup vs baseline: 1.3574x; 1.2670x over previous
#include <cuda_runtime.h>
#include <cuda_bf16.h>
#include <cstdint>

// GRU_66314295050287 on GB300 (sm_103a) — R12: R9 + triple buffer, depth-2
// prefetch. Evidence across R9/R10/R11: perf tracks outstanding bytes per
// warp (6KB -> 18.9us, 3KB -> ~30us), not occupancy. This round doubles
// steady-state in-flight to ~12KB/warp: while computing chunk c, chunks c+1
// and c+2 are both in the cp.async queue (wait_group 2).
// Block = 32 threads = 32 seqs; 8 chunks of F=4; NBUF=3.

#define T_DIM        12
#define FE_DIM       32
#define SEQ_PER_BLK  32
#define NTHREADS     32
#define CHUNK_F      4
#define NCHUNKS      (FE_DIM / CHUNK_F)          // 8
#define CHUNK_FLOATS (CHUNK_F * T_DIM)           // 48
#define CHUNK_VEC4   (CHUNK_FLOATS / 4)          // 12 float4 per seq per chunk
#define SSTRIDE      52                          // 52%32=20 -> conflict-free LDS.128
#define NBUF         3
#define BUF_FLOATS   (SEQ_PER_BLK * SSTRIDE)     // 1664 floats per buffer
#define SEQ_VEC4     96                          // 1536 B per sequence

__device__ __forceinline__ float fast_sigmoid(float x) {
    return 1.0f / (1.0f + __expf(-x));
}
__device__ __forceinline__ float fast_tanh(float x) {
    float e = __expf(2.0f * x);
    return 1.0f - 2.0f / (1.0f + e);
}

__device__ __forceinline__ void cp_async16(unsigned int saddr, const void* gptr) {
    asm volatile("cp.async.cg.shared.global [%0], [%1], 16;\n" :: "r"(saddr), "l"(gptr));
}
__device__ __forceinline__ void cp_commit() {
    asm volatile("cp.async.commit_group;\n");
}
template <int N>
__device__ __forceinline__ void cp_wait() {
    asm volatile("cp.async.wait_group %0;\n" :: "n"(N));
}

extern __shared__ float smem[];

__global__ void __launch_bounds__(NTHREADS, 11)
gru_kernel(const float* __restrict__ x,
           const float* __restrict__ w_ih,   // [3][32]
           const float* __restrict__ w_hh,   // [3][1]
           const float* __restrict__ b_ih,   // [3]
           const float* __restrict__ b_hh,   // [3]
           const float* __restrict__ lin_w,  // [3][12]
           const float* __restrict__ lin_b,  // [3]
           float* __restrict__ out)          // [M][3]
{
    float* buf0  = smem;                        // NBUF x BUF_FLOATS
    float* s_wih = smem + NBUF * BUF_FLOATS;    // 96
    float* s_lw  = s_wih + 96;                  // 36

    const int tid = threadIdx.x;
#pragma unroll
    for (int i = tid; i < 96; i += NTHREADS) s_wih[i] = w_ih[i];
#pragma unroll
    for (int i = tid; i < 36; i += NTHREADS) s_lw[i] = lin_w[i];

    const int m0 = blockIdx.x * SEQ_PER_BLK;
    const float4* __restrict__ x4 = reinterpret_cast<const float4*>(x);
    const unsigned int sbase = (unsigned int)__cvta_generic_to_shared(buf0);

    // One chunk = 32 seq x 12 contiguous float4 (192 B per seq) -> 12 per lane.
    // Consecutive lanes hit consecutive float4s: each warp op covers 512
    // contiguous bytes; every touched line fully consumed.
    auto issue_chunk = [&](int c, int b) {
#pragma unroll
        for (int k = 0; k < (SEQ_PER_BLK * CHUNK_VEC4) / NTHREADS; ++k) {
            int i  = k * NTHREADS + tid;
            int ms = i / CHUNK_VEC4;
            int q  = i - ms * CHUNK_VEC4;
            const void* g = (const void*)(x4 + (long)(m0 + ms) * SEQ_VEC4 + c * CHUNK_VEC4 + q);
            unsigned int s = sbase + (unsigned int)((b * BUF_FLOATS + ms * SSTRIDE + q * 4) * 4);
            cp_async16(s, g);
        }
        cp_commit();
    };

    const float bi0 = b_ih[0], bi1 = b_ih[1], bi2 = b_ih[2];
    float gx0[T_DIM], gx1[T_DIM], gx2[T_DIM];
#pragma unroll
    for (int t = 0; t < T_DIM; ++t) { gx0[t] = bi0; gx1[t] = bi1; gx2[t] = bi2; }

    // Prime the pipeline: chunks 0 and 1 in flight before any wait.
    issue_chunk(0, 0);
    issue_chunk(1, 1);

#pragma unroll
    for (int c = 0; c < NCHUNKS; ++c) {
        // Buffer (c+2)%3 was consumed at iteration c-1 (trailing barrier) ->
        // safe to refill. Then wait until chunk c has landed, leaving chunks
        // c+1 and c+2 (12 KB) outstanding during this iteration's compute.
        if (c + 2 < NCHUNKS) {
            issue_chunk(c + 2, (c + 2) % NBUF);
            cp_wait<2>();
        } else if (c + 1 < NCHUNKS) {
            cp_wait<1>();
        } else {
            cp_wait<0>();
        }
        __syncthreads();            // 1-warp block: BAR floor; chunk c visible

        const float* my = buf0 + (c % NBUF) * BUF_FLOATS + tid * SSTRIDE;
#pragma unroll
        for (int fl = 0; fl < CHUNK_F; ++fl) {
            int f = c * CHUNK_F + fl;
            float w0 = s_wih[f];
            float w1 = s_wih[32 + f];
            float w2 = s_wih[64 + f];
            float4 a = reinterpret_cast<const float4*>(my + fl * T_DIM)[0];
            float4 b = reinterpret_cast<const float4*>(my + fl * T_DIM)[1];
            float4 d = reinterpret_cast<const float4*>(my + fl * T_DIM)[2];
            float xt[T_DIM] = {a.x, a.y, a.z, a.w, b.x, b.y, b.z, b.w, d.x, d.y, d.z, d.w};
#pragma unroll
            for (int t = 0; t < T_DIM; ++t) {
                gx0[t] = fmaf(xt[t], w0, gx0[t]);
                gx1[t] = fmaf(xt[t], w1, gx1[t]);
                gx2[t] = fmaf(xt[t], w2, gx2[t]);
            }
        }
        __syncthreads();            // buffer c consumed -> refillable
    }

    // Scalar-hidden GRU recurrence + relu + linear head.
    const float wh0 = w_hh[0], wh1 = w_hh[1], wh2 = w_hh[2];
    const float bh0 = b_hh[0], bh1 = b_hh[1], bh2 = b_hh[2];
    float o0 = lin_b[0], o1 = lin_b[1], o2 = lin_b[2];
    float h = 0.0f;
#pragma unroll
    for (int t = 0; t < T_DIM; ++t) {
        float r = fast_sigmoid(gx0[t] + wh0 * h + bh0);
        float z = fast_sigmoid(gx1[t] + wh1 * h + bh1);
        float n = fast_tanh(gx2[t] + r * (wh2 * h + bh2));
        h = (1.0f - z) * n + z * h;
        float hr = fmaxf(h, 0.0f);
        o0 = fmaf(hr, s_lw[t],       o0);
        o1 = fmaf(hr, s_lw[12 + t],  o1);
        o2 = fmaf(hr, s_lw[24 + t],  o2);
    }

    // Coalesced epilogue: stage [32][3] floats in smem, write 24 float4.
    float* s_out = buf0;            // reuse (trailing barrier covered final reads)
    s_out[tid * 3 + 0] = o0;        // stride 3 coprime with 32 -> conflict-free
    s_out[tid * 3 + 1] = o1;
    s_out[tid * 3 + 2] = o2;
    __syncthreads();
    if (tid < (SEQ_PER_BLK * 3) / 4) {
        reinterpret_cast<float4*>(out + (long)m0 * 3)[tid] =
            reinterpret_cast<const float4*>(s_out)[tid];
    }
}

extern "C" void kernel_launch(void* const* d_in, const int* in_sizes, int n_in,
                              void* d_out, int out_size) {
    const float* x     = (const float*)d_in[0];
    const float* w_ih  = (const float*)d_in[1];
    const float* w_hh  = (const float*)d_in[2];
    const float* b_ih  = (const float*)d_in[3];
    const float* b_hh  = (const float*)d_in[4];
    const float* lin_w = (const float*)d_in[5];
    const float* lin_b = (const float*)d_in[6];
    float* out = (float*)d_out;

    const int M = in_sizes[0] / (FE_DIM * T_DIM);   // 65536
    const int grid = M / SEQ_PER_BLK;               // 2048

    const size_t smem_bytes = (size_t)(NBUF * BUF_FLOATS + 96 + 36) * sizeof(float);
    cudaFuncSetAttribute(gru_kernel, cudaFuncAttributeMaxDynamicSharedMemorySize,
                         (int)smem_bytes);

    gru_kernel<<<grid, NTHREADS, smem_bytes>>>(x, w_ih, w_hh, b_ih, b_hh,
                                               lin_w, lin_b, out);
}

// round 13
// speedup vs baseline: 1.5155x; 1.1165x over previous
#include <cuda_runtime.h>
#include <cuda_bf16.h>
#include <cstdint>

// GRU_66314295050287 on GB300 (sm_103a) — R13: quad-buffer, depth-3 prefetch,
// full residency. Constraint web from R9..R12: need ALL 2048 one-warp blocks
// resident (13.8/SM, single wave) -> smem <= 16.3KB/block; within that budget
// maximize cp.async bytes in flight per warp. CF=2 chunks (96B/seq = 3 exact
// sectors), NBUF=4 (power-of-2 masks), wait_group 3 -> 3 chunks (~10.8KB)
// outstanding during every compute phase (R9 had 6KB at depth 1).

#define T_DIM        12
#define FE_DIM       32
#define SEQ_PER_BLK  32
#define NTHREADS     32
#define CHUNK_F      2
#define NCHUNKS      (FE_DIM / CHUNK_F)          // 16
#define CHUNK_FLOATS (CHUNK_F * T_DIM)           // 24
#define CHUNK_VEC4   (CHUNK_FLOATS / 4)          // 6 float4 per seq per chunk
#define SSTRIDE      28                          // 28l mod 32 distinct per 8-lane phase
#define NBUF         4
#define BUF_FLOATS   (SEQ_PER_BLK * SSTRIDE)     // 896 floats = 3584 B per buffer
#define SEQ_VEC4     96                          // 1536 B per sequence

__device__ __forceinline__ float fast_sigmoid(float x) {
    return 1.0f / (1.0f + __expf(-x));
}
__device__ __forceinline__ float fast_tanh(float x) {
    float e = __expf(2.0f * x);
    return 1.0f - 2.0f / (1.0f + e);
}

__device__ __forceinline__ void cp_async16(unsigned int saddr, const void* gptr) {
    asm volatile("cp.async.cg.shared.global [%0], [%1], 16;\n" :: "r"(saddr), "l"(gptr));
}
__device__ __forceinline__ void cp_commit() {
    asm volatile("cp.async.commit_group;\n");
}
template <int N>
__device__ __forceinline__ void cp_wait() {
    asm volatile("cp.async.wait_group %0;\n" :: "n"(N));
}

extern __shared__ float smem[];

__global__ void __launch_bounds__(NTHREADS, 14)
gru_kernel(const float* __restrict__ x,
           const float* __restrict__ w_ih,   // [3][32]
           const float* __restrict__ w_hh,   // [3][1]
           const float* __restrict__ b_ih,   // [3]
           const float* __restrict__ b_hh,   // [3]
           const float* __restrict__ lin_w,  // [3][12]
           const float* __restrict__ lin_b,  // [3]
           float* __restrict__ out)          // [M][3]
{
    float* buf0  = smem;                        // NBUF x BUF_FLOATS
    float* s_wih = smem + NBUF * BUF_FLOATS;    // 96
    float* s_lw  = s_wih + 96;                  // 36

    const int tid = threadIdx.x;
#pragma unroll
    for (int i = tid; i < 96; i += NTHREADS) s_wih[i] = w_ih[i];
#pragma unroll
    for (int i = tid; i < 36; i += NTHREADS) s_lw[i] = lin_w[i];

    const int m0 = blockIdx.x * SEQ_PER_BLK;
    const float4* __restrict__ x4 = reinterpret_cast<const float4*>(x);
    const unsigned int sbase = (unsigned int)__cvta_generic_to_shared(buf0);

    // One chunk = 32 seq x 6 contiguous float4 (96 B / seq, sector-aligned:
    // c*96 is a multiple of 32 -> exactly 3 sectors, zero over-fetch).
    // 192 float4 -> 6 per lane.
    auto issue_chunk = [&](int c, int b) {
#pragma unroll
        for (int k = 0; k < (SEQ_PER_BLK * CHUNK_VEC4) / NTHREADS; ++k) {
            int i  = k * NTHREADS + tid;
            int ms = i / CHUNK_VEC4;
            int q  = i - ms * CHUNK_VEC4;
            const void* g = (const void*)(x4 + (long)(m0 + ms) * SEQ_VEC4 + c * CHUNK_VEC4 + q);
            unsigned int s = sbase + (unsigned int)((b * BUF_FLOATS + ms * SSTRIDE + q * 4) * 4);
            cp_async16(s, g);
        }
        cp_commit();
    };

    const float bi0 = b_ih[0], bi1 = b_ih[1], bi2 = b_ih[2];
    float gx0[T_DIM], gx1[T_DIM], gx2[T_DIM];
#pragma unroll
    for (int t = 0; t < T_DIM; ++t) { gx0[t] = bi0; gx1[t] = bi1; gx2[t] = bi2; }

    // Prime: chunks 0..2 in flight before the first wait.
    issue_chunk(0, 0);
    issue_chunk(1, 1);
    issue_chunk(2, 2);

#pragma unroll
    for (int c = 0; c < NCHUNKS; ++c) {
        // Refill buffer (c+3)&3 = (c-1)&3: consumed at iteration c-1, trailing
        // barrier there makes it safe. Then wait for chunk c, leaving chunks
        // c+1..c+3 (~10.8 KB) outstanding during this compute phase.
        if (c + 3 < NCHUNKS) {
            issue_chunk(c + 3, (c + 3) & (NBUF - 1));
            cp_wait<3>();
        } else if (c + 2 < NCHUNKS) {
            cp_wait<2>();
        } else if (c + 1 < NCHUNKS) {
            cp_wait<1>();
        } else {
            cp_wait<0>();
        }
        __syncthreads();            // 1-warp block: BAR floor; chunk c visible

        const float* my = buf0 + (c & (NBUF - 1)) * BUF_FLOATS + tid * SSTRIDE;
#pragma unroll
        for (int fl = 0; fl < CHUNK_F; ++fl) {
            int f = c * CHUNK_F + fl;
            float w0 = s_wih[f];
            float w1 = s_wih[32 + f];
            float w2 = s_wih[64 + f];
            float4 a = reinterpret_cast<const float4*>(my + fl * T_DIM)[0];
            float4 b = reinterpret_cast<const float4*>(my + fl * T_DIM)[1];
            float4 d = reinterpret_cast<const float4*>(my + fl * T_DIM)[2];
            float xt[T_DIM] = {a.x, a.y, a.z, a.w, b.x, b.y, b.z, b.w, d.x, d.y, d.z, d.w};
#pragma unroll
            for (int t = 0; t < T_DIM; ++t) {
                gx0[t] = fmaf(xt[t], w0, gx0[t]);
                gx1[t] = fmaf(xt[t], w1, gx1[t]);
                gx2[t] = fmaf(xt[t], w2, gx2[t]);
            }
        }
        __syncthreads();            // buffer c consumed -> refillable
    }

    // Scalar-hidden GRU recurrence + relu + linear head.
    const float wh0 = w_hh[0], wh1 = w_hh[1], wh2 = w_hh[2];
    const float bh0 = b_hh[0], bh1 = b_hh[1], bh2 = b_hh[2];
    float o0 = lin_b[0], o1 = lin_b[1], o2 = lin_b[2];
    float h = 0.0f;
#pragma unroll
    for (int t = 0; t < T_DIM; ++t) {
        float r = fast_sigmoid(gx0[t] + wh0 * h + bh0);
        float z = fast_sigmoid(gx1[t] + wh1 * h + bh1);
        float n = fast_tanh(gx2[t] + r * (wh2 * h + bh2));
        h = (1.0f - z) * n + z * h;
        float hr = fmaxf(h, 0.0f);
        o0 = fmaf(hr, s_lw[t],       o0);
        o1 = fmaf(hr, s_lw[12 + t],  o1);
        o2 = fmaf(hr, s_lw[24 + t],  o2);
    }

    // Coalesced epilogue: stage [32][3] floats in smem, write 24 float4.
    float* s_out = buf0;            // reuse (trailing barrier covered final reads)
    s_out[tid * 3 + 0] = o0;        // stride 3 coprime with 32 -> conflict-free
    s_out[tid * 3 + 1] = o1;
    s_out[tid * 3 + 2] = o2;
    __syncthreads();
    if (tid < (SEQ_PER_BLK * 3) / 4) {
        reinterpret_cast<float4*>(out + (long)m0 * 3)[tid] =
            reinterpret_cast<const float4*>(s_out)[tid];
    }
}

extern "C" void kernel_launch(void* const* d_in, const int* in_sizes, int n_in,
                              void* d_out, int out_size) {
    const float* x     = (const float*)d_in[0];
    const float* w_ih  = (const float*)d_in[1];
    const float* w_hh  = (const float*)d_in[2];
    const float* b_ih  = (const float*)d_in[3];
    const float* b_hh  = (const float*)d_in[4];
    const float* lin_w = (const float*)d_in[5];
    const float* lin_b = (const float*)d_in[6];
    float* out = (float*)d_out;

    const int M = in_sizes[0] / (FE_DIM * T_DIM);   // 65536
    const int grid = M / SEQ_PER_BLK;               // 2048

    const size_t smem_bytes = (size_t)(NBUF * BUF_FLOATS + 96 + 36) * sizeof(float);
    cudaFuncSetAttribute(gru_kernel, cudaFuncAttributeMaxDynamicSharedMemorySize,
                         (int)smem_bytes);

    gru_kernel<<<grid, NTHREADS, smem_bytes>>>(x, w_ih, w_hh, b_ih, b_hh,
                                               lin_w, lin_b, out);
}